// round 11
// baseline (speedup 1.0000x reference)
#include <cuda_runtime.h>
#include <stdint.h>

// MeanAggregator: out[b, :] = mean over {neighbours[b,0..9], nodes[b]} of features[idx, :]
// B = 100000, K = 10, N = 1000000, D = 128 (fp32). Indices int32 (JAX x64 disabled).
//
// HALF D-split (2 passes x 256 B per row): misses are 256B-contiguous -> 79.5% DRAM
// util (measured R10). Footprint 171 MB > L2 (126 MB) -> repeat hit rate bounded by
// residency C/W = 0.74; measured 0.66. This round: fractional evict_last (0.75) policy
// on feature gathers pins ~3/4 of the feature stream resident and demotes index/output
// churn, targeting the 0.66 -> 0.74 gap (~17 MB DRAM traffic).
//
// Warp = 2 rows: 2 subgroups of 16 lanes; lane = one float4 of the 16-float4 half-row.
// 11 gathers front-batched per lane. Output via st.global.wt (L2 write-bypass).

#define B_NODES   100000
#define K_NEIGH   10
#define D_DIM     128
#define D_VEC     (D_DIM / 4)    // 32 float4 per row
#define H_VEC     16             // 16 float4 per half

__device__ __forceinline__ uint64_t make_policy_frac_el() {
    uint64_t policy;
    asm("createpolicy.fractional.L2::evict_last.L2::evict_first.b64 %0, 0.75;"
        : "=l"(policy));
    return policy;
}

__device__ __forceinline__ float4 ldg_hint(const float4* p, uint64_t policy) {
    float4 v;
    asm volatile("ld.global.nc.L2::cache_hint.v4.f32 {%0, %1, %2, %3}, [%4], %5;"
                 : "=f"(v.x), "=f"(v.y), "=f"(v.z), "=f"(v.w)
                 : "l"(p), "l"(policy));
    return v;
}

__device__ __forceinline__ void stg_wt(float4* p, float4 v) {
    asm volatile("st.global.wt.v4.f32 [%0], {%1, %2, %3, %4};"
                 :: "l"(p), "f"(v.x), "f"(v.y), "f"(v.z), "f"(v.w)
                 : "memory");
}

__global__ __launch_bounds__(256, 4)
void mean_agg_kernel(const int*    __restrict__ nodes,
                     const int*    __restrict__ neighbours,
                     const float4* __restrict__ features,
                     float4*       __restrict__ out)
{
    const int warp = (blockIdx.x * blockDim.x + threadIdx.x) >> 5;  // 0..49999
    const int lane = threadIdx.x & 31;
    const int sub  = lane >> 4;        // subgroup 0..1 -> row offset
    const int sl   = lane & 15;        // float4 slot within half-row
    const int q    = blockIdx.y;       // feature-dim half (slowest-varying)

    const int row = warp * 2 + sub;
    if (row >= B_NODES) return;

    const uint64_t policy = make_policy_frac_el();

    // 11 row indices for this subgroup's row (converged within subgroup).
    int idx[K_NEIGH + 1];
#pragma unroll
    for (int k = 0; k < K_NEIGH; ++k)
        idx[k] = __ldcs(&neighbours[row * K_NEIGH + k]);
    idx[K_NEIGH] = __ldcs(&nodes[row]);

    const float4* fq = features + q * H_VEC + sl;

    // Front-batch 11 independent LDG.128 gathers (256B contiguous per subgroup).
    float4 v[K_NEIGH + 1];
#pragma unroll
    for (int k = 0; k < K_NEIGH + 1; ++k)
        v[k] = ldg_hint(fq + (long long)idx[k] * D_VEC, policy);

    float4 acc = make_float4(0.f, 0.f, 0.f, 0.f);
#pragma unroll
    for (int k = 0; k < K_NEIGH + 1; ++k) {
        acc.x += v[k].x;
        acc.y += v[k].y;
        acc.z += v[k].z;
        acc.w += v[k].w;
    }

    const float s = 1.0f / (float)(K_NEIGH + 1);
    acc.x *= s; acc.y *= s; acc.z *= s; acc.w *= s;

    stg_wt(&out[(long long)row * D_VEC + q * H_VEC + sl], acc);
}

extern "C" void kernel_launch(void* const* d_in, const int* in_sizes, int n_in,
                              void* d_out, int out_size)
{
    const int*    nodes      = (const int*)d_in[0];
    const int*    neighbours = (const int*)d_in[1];
    const float4* features   = (const float4*)d_in[2];
    float4*       out        = (float4*)d_out;

    const int threads = 256;
    const int warps_needed = (B_NODES + 1) / 2;                       // 50000
    dim3 grid((warps_needed * 32 + threads - 1) / threads, 2);        // 6250 x 2
    mean_agg_kernel<<<grid, threads>>>(nodes, neighbours, features, out);
}

// round 12
// speedup vs baseline: 1.0496x; 1.0496x over previous
#include <cuda_runtime.h>
#include <stdint.h>

// MeanAggregator: out[b, :] = mean over {neighbours[b,0..9], nodes[b]} of features[idx, :]
// B = 100000, K = 10, N = 1000000, D = 128 (fp32). Indices int32 (JAX x64 disabled).
//
// HALF D-split (2 passes x 256 B per row): 256B-contiguous misses -> 79.5% DRAM util
// (measured). Footprint 171 MB > L2 -> 66% repeat hits (measured, = LRU bound; policy
// steering neutral per R11). This round probes CONCURRENCY on this config: 6+5 gather
// batches cut live regs so launch_bounds(256,6) yields 6 CTAs/SM (48 warps), raising
// in-flight DRAM bytes ~50% to test whether 256B-grain util can approach its ceiling.
//
// Warp = 2 rows: 2 subgroups of 16 lanes; lane = one float4 of the 16-float4 half-row.
// Output via st.global.wt (L2 write-bypass), indices streaming (__ldcs).

#define B_NODES   100000
#define K_NEIGH   10
#define D_DIM     128
#define D_VEC     (D_DIM / 4)    // 32 float4 per row
#define H_VEC     16             // 16 float4 per half
#define BATCH1    6
#define BATCH2    5              // BATCH1 + BATCH2 = K_NEIGH + 1

__device__ __forceinline__ void stg_wt(float4* p, float4 v) {
    asm volatile("st.global.wt.v4.f32 [%0], {%1, %2, %3, %4};"
                 :: "l"(p), "f"(v.x), "f"(v.y), "f"(v.z), "f"(v.w)
                 : "memory");
}

__global__ __launch_bounds__(256, 6)
void mean_agg_kernel(const int*    __restrict__ nodes,
                     const int*    __restrict__ neighbours,
                     const float4* __restrict__ features,
                     float4*       __restrict__ out)
{
    const int warp = (blockIdx.x * blockDim.x + threadIdx.x) >> 5;  // 0..49999
    const int lane = threadIdx.x & 31;
    const int sub  = lane >> 4;        // subgroup 0..1 -> row offset
    const int sl   = lane & 15;        // float4 slot within half-row
    const int q    = blockIdx.y;       // feature-dim half (slowest-varying)

    const int row = warp * 2 + sub;
    if (row >= B_NODES) return;

    // 11 row indices for this subgroup's row (converged within subgroup).
    int idx[K_NEIGH + 1];
#pragma unroll
    for (int k = 0; k < K_NEIGH; ++k)
        idx[k] = __ldcs(&neighbours[row * K_NEIGH + k]);
    idx[K_NEIGH] = __ldcs(&nodes[row]);

    const float4* fq = features + q * H_VEC + sl;

    float4 acc = make_float4(0.f, 0.f, 0.f, 0.f);

    // Batch 1: 6 independent LDG.128 gathers (256B contiguous per subgroup).
    {
        float4 v[BATCH1];
#pragma unroll
        for (int k = 0; k < BATCH1; ++k)
            v[k] = __ldg(fq + (long long)idx[k] * D_VEC);
#pragma unroll
        for (int k = 0; k < BATCH1; ++k) {
            acc.x += v[k].x; acc.y += v[k].y;
            acc.z += v[k].z; acc.w += v[k].w;
        }
    }

    // Batch 2: remaining 5 gathers.
    {
        float4 v[BATCH2];
#pragma unroll
        for (int k = 0; k < BATCH2; ++k)
            v[k] = __ldg(fq + (long long)idx[BATCH1 + k] * D_VEC);
#pragma unroll
        for (int k = 0; k < BATCH2; ++k) {
            acc.x += v[k].x; acc.y += v[k].y;
            acc.z += v[k].z; acc.w += v[k].w;
        }
    }

    const float s = 1.0f / (float)(K_NEIGH + 1);
    acc.x *= s; acc.y *= s; acc.z *= s; acc.w *= s;

    stg_wt(&out[(long long)row * D_VEC + q * H_VEC + sl], acc);
}

extern "C" void kernel_launch(void* const* d_in, const int* in_sizes, int n_in,
                              void* d_out, int out_size)
{
    const int*    nodes      = (const int*)d_in[0];
    const int*    neighbours = (const int*)d_in[1];
    const float4* features   = (const float4*)d_in[2];
    float4*       out        = (float4*)d_out;

    const int threads = 256;
    const int warps_needed = (B_NODES + 1) / 2;                       // 50000
    dim3 grid((warps_needed * 32 + threads - 1) / threads, 2);        // 6250 x 2
    mean_agg_kernel<<<grid, threads>>>(nodes, neighbours, features, out);
}